// round 13
// baseline (speedup 1.0000x reference)
#include <cuda_runtime.h>
#include <cstdint>

// NATTEN 1D attention, fp32, TF32 tensor cores, FUSED softmax-PV.
// B=2, L=2048, D=512, H=8, hd=64, K=63.
// CTA: 64 queries, 256 threads (8 warps = 4 qgroups x 2 roles).
// Warp (qg, role): GEMM1 over its band half (role0: tiles 0..5, role1: 6..10),
// then per tile: exp2+mask -> quad-shuffle P C-frag into A-frag -> 8 mma into
// full-width oacc. No P smem, no mid barrier. Partial O + denom exchanged via
// smem once at the end; role0 combines, normalizes, stores.

#define BB 2
#define LL 2048
#define HH 8
#define HD 64
#define DD 512
#define KK 63
#define HALF 31
#define QTILE 64
#define THREADS 256
#define WROWS 136              // max band row = 135 (qg3 role1 tile 16, +4)
#define WPITCH 68              // % 32 == 4 -> conflict-free GEMM1 B loads
#define XPITCH 68              // exchange pitch; cols 0..63 frag, col 64 denom
#define SCALE2 0.1803368801f   // 64^-0.5 * log2(e); exp == exp2f

#define SM_W (WROWS * WPITCH)          // 9248 floats
#define SM_X (64 * XPITCH)             // 4352 floats (4 qg x 16 rows)
#define SMEM_BYTES ((SM_W + SM_X) * 4) // 54400 B -> 3 CTAs/SM

__device__ __forceinline__ uint32_t tf32_rna(float x) {
    uint32_t r;
    asm("cvt.rna.tf32.f32 %0, %1;" : "=r"(r) : "f"(x));
    return r;
}
__device__ __forceinline__ float tf32f(float x) {
    return __uint_as_float(tf32_rna(x));
}

__device__ __forceinline__ void mma_tf32(float c[4], const uint32_t a[4], const uint32_t b[2]) {
    asm("mma.sync.aligned.m16n8k8.row.col.f32.tf32.tf32.f32 "
        "{%0,%1,%2,%3}, {%4,%5,%6,%7}, {%8,%9}, {%0,%1,%2,%3};"
        : "+f"(c[0]), "+f"(c[1]), "+f"(c[2]), "+f"(c[3])
        : "r"(a[0]), "r"(a[1]), "r"(a[2]), "r"(a[3]),
          "r"(b[0]), "r"(b[1]));
}

// GEMM1 (ks-outer, independent accumulators) + fused exp/shuffle/PV over
// NTJ band tiles starting at absolute tile index nt0j.
template <int NTJ>
__device__ __forceinline__ void band_compute(
    float (*oacc)[4], float& sum0, float& sum1,
    const float* W, int nt0j,
    const float* qr0, const float* qr1,
    int o0, int o1, int g, int t, int lane)
{
    float sacc[NTJ][4];
    #pragma unroll
    for (int j = 0; j < NTJ; j++)
        #pragma unroll
        for (int i = 0; i < 4; i++) sacc[j][i] = 0.f;

    // ---- GEMM1: S band ----
    const float* wband = W + (nt0j * 8 + g) * WPITCH + t;
    #pragma unroll
    for (int ks = 0; ks < 8; ks++) {
        uint32_t a[4];
        a[0] = __float_as_uint(qr0[ks * 8 + t] * SCALE2);
        a[1] = __float_as_uint(qr1[ks * 8 + t] * SCALE2);
        a[2] = __float_as_uint(qr0[ks * 8 + t + 4] * SCALE2);
        a[3] = __float_as_uint(qr1[ks * 8 + t + 4] * SCALE2);
        uint32_t bb[2 * NTJ];
        const float* p = wband + ks * 8;
        #pragma unroll
        for (int j = 0; j < NTJ; j++) {
            bb[2 * j]     = __float_as_uint(p[0]);
            bb[2 * j + 1] = __float_as_uint(p[4]);
            p += 8 * WPITCH;
        }
        #pragma unroll
        for (int j = 0; j < NTJ; j++)
            mma_tf32(sacc[j], a, &bb[2 * j]);
    }

    // ---- Fused: per tile j: exp -> shuffle C-frag to A-frag -> 8 mma ----
    const int srcA = (lane & ~3) | (t >> 1);
    const int srcB = srcA + 2;
    const bool hi = (t & 1);

    #pragma unroll
    for (int j = 0; j < NTJ; j++) {
        int j0 = (nt0j + j) * 8 + 2 * t;
        int j1 = j0 + 1;
        float e00 = ((unsigned)(j0 - o0) < (unsigned)KK) ? tf32f(exp2f(sacc[j][0])) : 0.f;
        float e01 = ((unsigned)(j1 - o0) < (unsigned)KK) ? tf32f(exp2f(sacc[j][1])) : 0.f;
        float e10 = ((unsigned)(j0 - o1) < (unsigned)KK) ? tf32f(exp2f(sacc[j][2])) : 0.f;
        float e11 = ((unsigned)(j1 - o1) < (unsigned)KK) ? tf32f(exp2f(sacc[j][3])) : 0.f;
        sum0 += e00 + e01;
        sum1 += e10 + e11;

        // Assemble P A-fragment (cols t, t+4 of rows g, g+8) from quad-mates.
        float xa0 = __shfl_sync(0xffffffffu, e00, srcA);
        float xa1 = __shfl_sync(0xffffffffu, e01, srcA);
        float xb0 = __shfl_sync(0xffffffffu, e10, srcA);
        float xb1 = __shfl_sync(0xffffffffu, e11, srcA);
        float xc0 = __shfl_sync(0xffffffffu, e00, srcB);
        float xc1 = __shfl_sync(0xffffffffu, e01, srcB);
        float xd0 = __shfl_sync(0xffffffffu, e10, srcB);
        float xd1 = __shfl_sync(0xffffffffu, e11, srcB);
        uint32_t pa[4];
        pa[0] = __float_as_uint(hi ? xa1 : xa0);   // P[g][t]
        pa[1] = __float_as_uint(hi ? xb1 : xb0);   // P[g+8][t]
        pa[2] = __float_as_uint(hi ? xc1 : xc0);   // P[g][t+4]
        pa[3] = __float_as_uint(hi ? xd1 : xd0);   // P[g+8][t+4]

        // PV: all 8 n-tiles; B from W rows (tile*8+t, +4), cols nt*8+g.
        const float* wr  = W + ((nt0j + j) * 8 + t) * WPITCH + g;
        const float* wr2 = wr + 4 * WPITCH;
        uint32_t wb[8];
        #pragma unroll
        for (int nt = 0; nt < 4; nt++) {
            wb[2 * nt]     = __float_as_uint(wr[nt * 8]);
            wb[2 * nt + 1] = __float_as_uint(wr2[nt * 8]);
        }
        #pragma unroll
        for (int nt = 0; nt < 4; nt++)
            mma_tf32(oacc[nt], pa, &wb[2 * nt]);
        #pragma unroll
        for (int nt = 0; nt < 4; nt++) {
            wb[2 * nt]     = __float_as_uint(wr[(nt + 4) * 8]);
            wb[2 * nt + 1] = __float_as_uint(wr2[(nt + 4) * 8]);
        }
        #pragma unroll
        for (int nt = 0; nt < 4; nt++)
            mma_tf32(oacc[nt + 4], pa, &wb[2 * nt]);
    }
}

__global__ __launch_bounds__(THREADS, 3)
void natten1d_tc(const float* __restrict__ x, float* __restrict__ out) {
    extern __shared__ float smem[];
    float* W = smem;                  // [WROWS][WPITCH], tf32-rounded
    float* X = smem + SM_W;           // exchange: 4 qg x [16][XPITCH]

    const int tile = blockIdx.x;      // 0..31
    const int h    = blockIdx.y;
    const int b    = blockIdx.z;
    const int tid  = threadIdx.x;
    const int lane = tid & 31;
    const int warp = tid >> 5;        // 0..7
    const int qg   = warp >> 1;       // 0..3
    const int role = warp & 1;        // 0: tiles 0..5; 1: tiles 6..10

    const int base   = tile * QTILE;
    const int origin = base - HALF;

    // ---- Stage W rows [origin, origin+136) clipped to [0,L), tf32-rounded ----
    const float* xb = x + ((size_t)b * LL) * DD + h * HD;
    for (int i = tid; i < WROWS * 16; i += THREADS) {
        int r = i >> 4;
        int c = i & 15;
        int gg = origin + r;
        float4 v = make_float4(0.f, 0.f, 0.f, 0.f);
        if ((unsigned)gg < (unsigned)LL)
            v = *(const float4*)(xb + (size_t)gg * DD + c * 4);
        v.x = tf32f(v.x); v.y = tf32f(v.y); v.z = tf32f(v.z); v.w = tf32f(v.w);
        *(float4*)(W + r * WPITCH + c * 4) = v;
    }
    __syncthreads();

    const int g = lane >> 2;
    const int t = lane & 3;
    const int q0 = qg * 16;

    int stf = base + q0 - HALF;
    if (stf < 0) stf = 0;
    if (stf > LL - KK) stf = LL - KK;
    const int nt0 = (stf - origin) >> 3;

    const int p0 = base + q0 + g;
    const int p1 = p0 + 8;
    int s0c = p0 - HALF; if (s0c < 0) s0c = 0; if (s0c > LL - KK) s0c = LL - KK;
    int s1c = p1 - HALF; if (s1c < 0) s1c = 0; if (s1c > LL - KK) s1c = LL - KK;
    const int o0 = s0c - origin;
    const int o1 = s1c - origin;

    const float* qr0 = W + (q0 + g + HALF) * WPITCH;
    const float* qr1 = qr0 + 8 * WPITCH;

    float oacc[8][4];
    #pragma unroll
    for (int nt = 0; nt < 8; nt++)
        #pragma unroll
        for (int i = 0; i < 4; i++) oacc[nt][i] = 0.f;
    float sum0 = 0.f, sum1 = 0.f;

    if (role == 0)
        band_compute<6>(oacc, sum0, sum1, W, nt0,     qr0, qr1, o0, o1, g, t, lane);
    else
        band_compute<5>(oacc, sum0, sum1, W, nt0 + 6, qr0, qr1, o0, o1, g, t, lane);

    // quad-reduce denominators (cols split across t)
    sum0 += __shfl_xor_sync(0xffffffffu, sum0, 1);
    sum0 += __shfl_xor_sync(0xffffffffu, sum0, 2);
    sum1 += __shfl_xor_sync(0xffffffffu, sum1, 1);
    sum1 += __shfl_xor_sync(0xffffffffu, sum1, 2);

    float* Xr0 = X + (qg * 16 + g) * XPITCH;
    float* Xr1 = Xr0 + 8 * XPITCH;

    // role1 publishes its partial O (fragment layout) + denominators
    if (role == 1) {
        #pragma unroll
        for (int nt = 0; nt < 8; nt++) {
            *(float2*)(Xr0 + nt * 8 + 2 * t) = make_float2(oacc[nt][0], oacc[nt][1]);
            *(float2*)(Xr1 + nt * 8 + 2 * t) = make_float2(oacc[nt][2], oacc[nt][3]);
        }
        if (t == 0) {
            Xr0[64] = sum0;
            Xr1[64] = sum1;
        }
    }

    __syncthreads();

    // role0 combines, normalizes, stores the full 16x64 block
    if (role == 0) {
        const float inv0 = 1.0f / (sum0 + Xr0[64]);
        const float inv1 = 1.0f / (sum1 + Xr1[64]);
        float* orow0 = out + ((size_t)(b * LL + p0)) * DD + h * HD;
        float* orow1 = out + ((size_t)(b * LL + p1)) * DD + h * HD;
        #pragma unroll
        for (int nt = 0; nt < 8; nt++) {
            float2 q0v = *(float2*)(Xr0 + nt * 8 + 2 * t);
            float2 q1v = *(float2*)(Xr1 + nt * 8 + 2 * t);
            int d0 = nt * 8 + 2 * t;
            *(float2*)(orow0 + d0) = make_float2((oacc[nt][0] + q0v.x) * inv0,
                                                 (oacc[nt][1] + q0v.y) * inv0);
            *(float2*)(orow1 + d0) = make_float2((oacc[nt][2] + q1v.x) * inv1,
                                                 (oacc[nt][3] + q1v.y) * inv1);
        }
    }
}

extern "C" void kernel_launch(void* const* d_in, const int* in_sizes, int n_in,
                              void* d_out, int out_size) {
    (void)in_sizes; (void)n_in; (void)out_size;
    const float* x = (const float*)d_in[0];
    float* out = (float*)d_out;

    cudaFuncSetAttribute(natten1d_tc,
                         cudaFuncAttributeMaxDynamicSharedMemorySize, SMEM_BYTES);

    dim3 grid(LL / QTILE, HH, BB);   // 32 x 8 x 2 = 512 CTAs, 3/SM
    natten1d_tc<<<grid, THREADS, SMEM_BYTES>>>(x, out);
}

// round 15
// speedup vs baseline: 1.1007x; 1.1007x over previous
#include <cuda_runtime.h>
#include <cstdint>

// NATTEN 1D attention, fp32, TF32 tensor cores, fused softmax-PV,
// minimal phase-locked unit: 4-warp CTAs, 1 warp = 16 queries, full band.
// B=2, L=2048, D=512, H=8, hd=64, K=63.
// Per warp: GEMM1 S(16x88 band) -> exp2+mask -> quad-shuffle C-frag into
// A-frag -> PV mma into full-width oacc -> normalize -> store.
// Only one __syncthreads (after staging). Smem = W slab only (static, 37KB)
// -> 4 CTAs/SM, warps on an SMSP come from 4 independent CTAs.

#define BB 2
#define LL 2048
#define HH 8
#define HD 64
#define DD 512
#define KK 63
#define HALF 31
#define QTILE 64
#define THREADS 128
#define WROWS 136              // max touched row = 135 (nt0<=6, tile 16)
#define WPITCH 68              // % 32 == 4 -> conflict-free fragment loads
#define NT 11
#define SCALE2 0.1803368801f   // 64^-0.5 * log2(e); exp == exp2f

__device__ __forceinline__ uint32_t tf32_rna(float x) {
    uint32_t r;
    asm("cvt.rna.tf32.f32 %0, %1;" : "=r"(r) : "f"(x));
    return r;
}
__device__ __forceinline__ float tf32f(float x) {
    return __uint_as_float(tf32_rna(x));
}

__device__ __forceinline__ void mma_tf32(float c[4], const uint32_t a[4], const uint32_t b[2]) {
    asm("mma.sync.aligned.m16n8k8.row.col.f32.tf32.tf32.f32 "
        "{%0,%1,%2,%3}, {%4,%5,%6,%7}, {%8,%9}, {%0,%1,%2,%3};"
        : "+f"(c[0]), "+f"(c[1]), "+f"(c[2]), "+f"(c[3])
        : "r"(a[0]), "r"(a[1]), "r"(a[2]), "r"(a[3]),
          "r"(b[0]), "r"(b[1]));
}

__global__ __launch_bounds__(THREADS, 4)
void natten1d_tc(const float* __restrict__ x, float* __restrict__ out) {
    __shared__ float W[WROWS * WPITCH];    // 36992 B, tf32-rounded values

    const int tile = blockIdx.x;           // 0..31
    const int h    = blockIdx.y;
    const int b    = blockIdx.z;
    const int tid  = threadIdx.x;
    const int lane = tid & 31;
    const int warp = tid >> 5;             // 0..3 = query group

    const int base   = tile * QTILE;
    const int origin = base - HALF;

    // ---- Stage W rows [origin, origin+136) clipped to [0,L), tf32-rounded ----
    const float* xb = x + ((size_t)b * LL) * DD + h * HD;
    for (int i = tid; i < WROWS * 16; i += THREADS) {
        int r = i >> 4;
        int c = i & 15;
        int gg = origin + r;
        float4 v = make_float4(0.f, 0.f, 0.f, 0.f);
        if ((unsigned)gg < (unsigned)LL)
            v = *(const float4*)(xb + (size_t)gg * DD + c * 4);
        v.x = tf32f(v.x); v.y = tf32f(v.y); v.z = tf32f(v.z); v.w = tf32f(v.w);
        *(float4*)(W + r * WPITCH + c * 4) = v;
    }
    __syncthreads();   // the ONLY cta-wide sync

    const int g = lane >> 2;   // 0..7
    const int t = lane & 3;    // 0..3
    const int q0 = warp * 16;

    int stf = base + q0 - HALF;
    if (stf < 0) stf = 0;
    if (stf > LL - KK) stf = LL - KK;
    const int nt0 = (stf - origin) >> 3;

    const int p0 = base + q0 + g;
    const int p1 = p0 + 8;
    int s0c = p0 - HALF; if (s0c < 0) s0c = 0; if (s0c > LL - KK) s0c = LL - KK;
    int s1c = p1 - HALF; if (s1c < 0) s1c = 0; if (s1c > LL - KK) s1c = LL - KK;
    const int o0 = s0c - origin;
    const int o1 = s1c - origin;

    const float* qr0 = W + (q0 + g + HALF) * WPITCH;
    const float* qr1 = qr0 + 8 * WPITCH;

    // ================= GEMM1: S band (ks-outer, independent accs) ========
    float sacc[NT][4];
    #pragma unroll
    for (int j = 0; j < NT; j++)
        #pragma unroll
        for (int i = 0; i < 4; i++) sacc[j][i] = 0.f;

    const float* wband = W + (nt0 * 8 + g) * WPITCH + t;
    #pragma unroll
    for (int ks = 0; ks < 8; ks++) {
        uint32_t a[4];
        a[0] = __float_as_uint(qr0[ks * 8 + t] * SCALE2);
        a[1] = __float_as_uint(qr1[ks * 8 + t] * SCALE2);
        a[2] = __float_as_uint(qr0[ks * 8 + t + 4] * SCALE2);
        a[3] = __float_as_uint(qr1[ks * 8 + t + 4] * SCALE2);
        uint32_t bb[2 * NT];
        const float* p = wband + ks * 8;
        #pragma unroll
        for (int j = 0; j < NT; j++) {
            bb[2 * j]     = __float_as_uint(p[0]);
            bb[2 * j + 1] = __float_as_uint(p[4]);
            p += 8 * WPITCH;
        }
        #pragma unroll
        for (int j = 0; j < NT; j++)
            mma_tf32(sacc[j], a, &bb[2 * j]);
    }

    // ======== Fused epilogue+PV: per tile exp2 -> shuffle -> 8 mma ========
    float oacc[8][4];
    #pragma unroll
    for (int nt = 0; nt < 8; nt++)
        #pragma unroll
        for (int i = 0; i < 4; i++) oacc[nt][i] = 0.f;
    float sum0 = 0.f, sum1 = 0.f;

    const int srcA = (lane & ~3) | (t >> 1);
    const int srcB = srcA + 2;
    const bool hi = (t & 1);

    #pragma unroll
    for (int j = 0; j < NT; j++) {
        int j0 = (nt0 + j) * 8 + 2 * t;
        int j1 = j0 + 1;
        float e00 = ((unsigned)(j0 - o0) < (unsigned)KK) ? tf32f(exp2f(sacc[j][0])) : 0.f;
        float e01 = ((unsigned)(j1 - o0) < (unsigned)KK) ? tf32f(exp2f(sacc[j][1])) : 0.f;
        float e10 = ((unsigned)(j0 - o1) < (unsigned)KK) ? tf32f(exp2f(sacc[j][2])) : 0.f;
        float e11 = ((unsigned)(j1 - o1) < (unsigned)KK) ? tf32f(exp2f(sacc[j][3])) : 0.f;
        sum0 += e00 + e01;
        sum1 += e10 + e11;

        // Assemble P A-fragment (cols t, t+4 of rows g, g+8) from quad-mates.
        float xa0 = __shfl_sync(0xffffffffu, e00, srcA);
        float xa1 = __shfl_sync(0xffffffffu, e01, srcA);
        float xb0 = __shfl_sync(0xffffffffu, e10, srcA);
        float xb1 = __shfl_sync(0xffffffffu, e11, srcA);
        float xc0 = __shfl_sync(0xffffffffu, e00, srcB);
        float xc1 = __shfl_sync(0xffffffffu, e01, srcB);
        float xd0 = __shfl_sync(0xffffffffu, e10, srcB);
        float xd1 = __shfl_sync(0xffffffffu, e11, srcB);
        uint32_t pa[4];
        pa[0] = __float_as_uint(hi ? xa1 : xa0);   // P[g][t]
        pa[1] = __float_as_uint(hi ? xb1 : xb0);   // P[g+8][t]
        pa[2] = __float_as_uint(hi ? xc1 : xc0);   // P[g][t+4]
        pa[3] = __float_as_uint(hi ? xd1 : xd0);   // P[g+8][t+4]

        // PV over all 8 n-tiles.
        const float* wr  = W + ((nt0 + j) * 8 + t) * WPITCH + g;
        const float* wr2 = wr + 4 * WPITCH;
        uint32_t wb[8];
        #pragma unroll
        for (int nt = 0; nt < 4; nt++) {
            wb[2 * nt]     = __float_as_uint(wr[nt * 8]);
            wb[2 * nt + 1] = __float_as_uint(wr2[nt * 8]);
        }
        #pragma unroll
        for (int nt = 0; nt < 4; nt++)
            mma_tf32(oacc[nt], pa, &wb[2 * nt]);
        #pragma unroll
        for (int nt = 0; nt < 4; nt++) {
            wb[2 * nt]     = __float_as_uint(wr[(nt + 4) * 8]);
            wb[2 * nt + 1] = __float_as_uint(wr2[(nt + 4) * 8]);
        }
        #pragma unroll
        for (int nt = 0; nt < 4; nt++)
            mma_tf32(oacc[nt + 4], pa, &wb[2 * nt]);
    }

    // ---- Denominators (quad reduce; cols split across t) ----
    sum0 += __shfl_xor_sync(0xffffffffu, sum0, 1);
    sum0 += __shfl_xor_sync(0xffffffffu, sum0, 2);
    sum1 += __shfl_xor_sync(0xffffffffu, sum1, 1);
    sum1 += __shfl_xor_sync(0xffffffffu, sum1, 2);
    const float inv0 = 1.0f / sum0;
    const float inv1 = 1.0f / sum1;

    // ================= Normalize + store =================
    float* orow0 = out + ((size_t)(b * LL + p0)) * DD + h * HD;
    float* orow1 = out + ((size_t)(b * LL + p1)) * DD + h * HD;
    #pragma unroll
    for (int nt = 0; nt < 8; nt++) {
        int d0 = nt * 8 + 2 * t;
        *(float2*)(orow0 + d0) = make_float2(oacc[nt][0] * inv0, oacc[nt][1] * inv0);
        *(float2*)(orow1 + d0) = make_float2(oacc[nt][2] * inv1, oacc[nt][3] * inv1);
    }
}

extern "C" void kernel_launch(void* const* d_in, const int* in_sizes, int n_in,
                              void* d_out, int out_size) {
    (void)in_sizes; (void)n_in; (void)out_size;
    const float* x = (const float*)d_in[0];
    float* out = (float*)d_out;

    dim3 grid(LL / QTILE, HH, BB);   // 32 x 8 x 2 = 512 CTAs, 4/SM capable
    natten1d_tc<<<grid, THREADS>>>(x, out);
}

// round 17
// speedup vs baseline: 1.1501x; 1.0448x over previous
#include <cuda_runtime.h>
#include <cstdint>

// NATTEN 1D attention, fp32, TF32 tensor cores, banded per-warp windows.
// B=2, L=2048, D=512, H=8, hd=64, K=63.  (R6 shape = empirical best.)
// CTA: 128 queries, 8 warps (16 queries each). W slab [200 x 64] staged RAW
// f32 (HW mma truncates to tf32). GEMM1 j-outer double-buffered B. Epilogue
// exp2+mask -> P tf32-rounded (consistent num/denom). GEMM2 double-buffered.

#define BB 2
#define LL 2048
#define HH 8
#define HD 64
#define DD 512
#define KK 63
#define HALF 31
#define QTILE 128
#define THREADS 256
#define WROWS 200              // max band reach: warp7 nt0=14 -> rows < 200
#define WPITCH 68              // % 32 == 4 -> conflict-free GEMM1 fragment loads
#define PP 100                 // % 32 == 4 -> conflict-free GEMM2 A (P) loads
#define NT 11                  // band tiles of 8 cols
#define SCALE2 0.1803368801f   // 64^-0.5 * log2(e); exp == exp2f

#define SM_W (WROWS * WPITCH)          // 13600 floats
#define SM_P (8 * 16 * PP)             // 12800 floats
#define SMEM_BYTES ((SM_W + SM_P) * 4) // 105600 B -> 2 CTAs/SM

__device__ __forceinline__ uint32_t tf32_rna(float x) {
    uint32_t r;
    asm("cvt.rna.tf32.f32 %0, %1;" : "=r"(r) : "f"(x));
    return r;
}
__device__ __forceinline__ float tf32f(float x) {
    return __uint_as_float(tf32_rna(x));
}

__device__ __forceinline__ void mma_tf32(float c[4], const uint32_t a[4], const uint32_t b[2]) {
    asm("mma.sync.aligned.m16n8k8.row.col.f32.tf32.tf32.f32 "
        "{%0,%1,%2,%3}, {%4,%5,%6,%7}, {%8,%9}, {%0,%1,%2,%3};"
        : "+f"(c[0]), "+f"(c[1]), "+f"(c[2]), "+f"(c[3])
        : "r"(a[0]), "r"(a[1]), "r"(a[2]), "r"(a[3]),
          "r"(b[0]), "r"(b[1]));
}

// GEMM1 B-fragment batch for tile j: 16 scalar LDS, conflict-free.
__device__ __forceinline__ void load_b1(uint32_t dst[16], const float* W,
                                        int nt0j, int g, int t) {
    const float* p = W + (nt0j * 8 + g) * WPITCH + t;
    #pragma unroll
    for (int ks = 0; ks < 8; ks++) {
        dst[2 * ks]     = __float_as_uint(p[ks * 8]);
        dst[2 * ks + 1] = __float_as_uint(p[ks * 8 + 4]);
    }
}

// GEMM2 B-fragment batch for k-tile j: 16 scalar LDS (2-way, accepted).
__device__ __forceinline__ void load_b2(uint32_t dst[16], const float* W,
                                        int nt0j, int g, int t) {
    const float* p = W + (nt0j * 8 + t) * WPITCH + g;
    #pragma unroll
    for (int nt = 0; nt < 8; nt++) {
        dst[2 * nt]     = __float_as_uint(p[nt * 8]);
        dst[2 * nt + 1] = __float_as_uint(p[4 * WPITCH + nt * 8]);
    }
}

// GEMM2 A (P) fragment: 4 scalar LDS, conflict-free (PP % 32 == 4).
__device__ __forceinline__ void load_pa(uint32_t dst[4], const float* Pr0,
                                        const float* Pr1, int j, int t) {
    dst[0] = __float_as_uint(Pr0[j * 8 + t]);
    dst[1] = __float_as_uint(Pr1[j * 8 + t]);
    dst[2] = __float_as_uint(Pr0[j * 8 + t + 4]);
    dst[3] = __float_as_uint(Pr1[j * 8 + t + 4]);
}

__global__ __launch_bounds__(THREADS, 2)
void natten1d_tc(const float* __restrict__ x, float* __restrict__ out) {
    extern __shared__ float smem[];
    float* W = smem;                 // [WROWS][WPITCH], raw f32
    float* P = smem + SM_W;          // 8 warps x [16][PP]

    const int tile = blockIdx.x;
    const int h    = blockIdx.y;
    const int b    = blockIdx.z;
    const int tid  = threadIdx.x;
    const int lane = tid & 31;
    const int warp = tid >> 5;

    const int base   = tile * QTILE;
    const int origin = base - HALF;

    // ---- Stage W rows [origin, origin+200) clipped to [0,L), RAW f32 ----
    const float* xb = x + ((size_t)b * LL) * DD + h * HD;
    for (int i = tid; i < WROWS * 16; i += THREADS) {
        int r = i >> 4;
        int c = i & 15;
        int g = origin + r;
        float4 v = make_float4(0.f, 0.f, 0.f, 0.f);
        if ((unsigned)g < (unsigned)LL)
            v = *(const float4*)(xb + (size_t)g * DD + c * 4);
        *(float4*)(W + r * WPITCH + c * 4) = v;
    }
    __syncthreads();

    const int g = lane >> 2;   // 0..7
    const int t = lane & 3;    // 0..3
    const int q0 = warp * 16;

    int stf = base + q0 - HALF;
    if (stf < 0) stf = 0;
    if (stf > LL - KK) stf = LL - KK;
    const int nt0 = (stf - origin) >> 3;

    const int p0 = base + q0 + g;
    const int p1 = p0 + 8;
    int s0c = p0 - HALF; if (s0c < 0) s0c = 0; if (s0c > LL - KK) s0c = LL - KK;
    int s1c = p1 - HALF; if (s1c < 0) s1c = 0; if (s1c > LL - KK) s1c = LL - KK;
    const int o0 = s0c - origin;
    const int o1 = s1c - origin;

    // ---- Preload A fragments (Q rows, prescaled by scale*log2e) ----
    const float* qr0 = W + (q0 + g + HALF) * WPITCH;
    const float* qr1 = qr0 + 8 * WPITCH;
    uint32_t A[8][4];
    #pragma unroll
    for (int ks = 0; ks < 8; ks++) {
        A[ks][0] = __float_as_uint(qr0[ks * 8 + t] * SCALE2);
        A[ks][1] = __float_as_uint(qr1[ks * 8 + t] * SCALE2);
        A[ks][2] = __float_as_uint(qr0[ks * 8 + t + 4] * SCALE2);
        A[ks][3] = __float_as_uint(qr1[ks * 8 + t + 4] * SCALE2);
    }

    // ================= GEMM1 (double-buffered B) =================
    float sacc[NT][4];
    #pragma unroll
    for (int j = 0; j < NT; j++)
        #pragma unroll
        for (int i = 0; i < 4; i++) sacc[j][i] = 0.f;

    uint32_t Bb[2][16];
    load_b1(Bb[0], W, nt0, g, t);
    #pragma unroll
    for (int j = 0; j < NT; j++) {
        if (j + 1 < NT) load_b1(Bb[(j + 1) & 1], W, nt0 + j + 1, g, t);
        uint32_t* cur = Bb[j & 1];
        #pragma unroll
        for (int ks = 0; ks < 8; ks++)
            mma_tf32(sacc[j], A[ks], &cur[2 * ks]);
    }

    // ====== Epilogue: P = tf32(exp2(S))*mask -> smem, partial sums ======
    float sum0 = 0.f, sum1 = 0.f;
    float* Pr0 = P + (warp * 16 + g) * PP;
    float* Pr1 = Pr0 + 8 * PP;
    #pragma unroll
    for (int j = 0; j < NT; j++) {
        int j0 = (nt0 + j) * 8 + 2 * t;
        int j1 = j0 + 1;
        float e00 = ((unsigned)(j0 - o0) < (unsigned)KK) ? tf32f(exp2f(sacc[j][0])) : 0.f;
        float e01 = ((unsigned)(j1 - o0) < (unsigned)KK) ? tf32f(exp2f(sacc[j][1])) : 0.f;
        float e10 = ((unsigned)(j0 - o1) < (unsigned)KK) ? tf32f(exp2f(sacc[j][2])) : 0.f;
        float e11 = ((unsigned)(j1 - o1) < (unsigned)KK) ? tf32f(exp2f(sacc[j][3])) : 0.f;
        sum0 += e00 + e01;
        sum1 += e10 + e11;
        int bc = j * 8 + 2 * t;
        *(float2*)(Pr0 + bc) = make_float2(e00, e01);
        *(float2*)(Pr1 + bc) = make_float2(e10, e11);
    }
    __syncwarp();   // P written by quad-mates, read cross-lane below

    // ================= GEMM2 (double-buffered A+B) =================
    float oacc[8][4];
    #pragma unroll
    for (int nt = 0; nt < 8; nt++)
        #pragma unroll
        for (int i = 0; i < 4; i++) oacc[nt][i] = 0.f;

    uint32_t PA[2][4], WB[2][16];
    load_pa(PA[0], Pr0, Pr1, 0, t);
    load_b2(WB[0], W, nt0, g, t);
    #pragma unroll
    for (int j = 0; j < NT; j++) {
        if (j + 1 < NT) {
            load_pa(PA[(j + 1) & 1], Pr0, Pr1, j + 1, t);
            load_b2(WB[(j + 1) & 1], W, nt0 + j + 1, g, t);
        }
        uint32_t* pa = PA[j & 1];
        uint32_t* wb = WB[j & 1];
        #pragma unroll
        for (int nt = 0; nt < 8; nt++)
            mma_tf32(oacc[nt], pa, &wb[2 * nt]);
    }

    // ---- Denominators (deferred reduction) ----
    sum0 += __shfl_xor_sync(0xffffffffu, sum0, 1);
    sum0 += __shfl_xor_sync(0xffffffffu, sum0, 2);
    sum1 += __shfl_xor_sync(0xffffffffu, sum1, 1);
    sum1 += __shfl_xor_sync(0xffffffffu, sum1, 2);
    const float inv0 = 1.0f / sum0;
    const float inv1 = 1.0f / sum1;

    // ================= Normalize + store =================
    float* orow0 = out + ((size_t)(b * LL + p0)) * DD + h * HD;
    float* orow1 = out + ((size_t)(b * LL + p1)) * DD + h * HD;
    #pragma unroll
    for (int nt = 0; nt < 8; nt++) {
        int d0 = nt * 8 + 2 * t;
        *(float2*)(orow0 + d0) = make_float2(oacc[nt][0] * inv0, oacc[nt][1] * inv0);
        *(float2*)(orow1 + d0) = make_float2(oacc[nt][2] * inv1, oacc[nt][3] * inv1);
    }
}

extern "C" void kernel_launch(void* const* d_in, const int* in_sizes, int n_in,
                              void* d_out, int out_size) {
    (void)in_sizes; (void)n_in; (void)out_size;
    const float* x = (const float*)d_in[0];
    float* out = (float*)d_out;

    cudaFuncSetAttribute(natten1d_tc,
                         cudaFuncAttributeMaxDynamicSharedMemorySize, SMEM_BYTES);

    dim3 grid(LL / QTILE, HH, BB);   // 16 x 8 x 2 = 256 CTAs
    natten1d_tc<<<grid, THREADS, SMEM_BYTES>>>(x, out);
}